// round 16
// baseline (speedup 1.0000x reference)
#include <cuda_runtime.h>
#include <cstdint>

// Problem constants (fixed shapes per reference)
#define B_DIM 4
#define P_DIM 2
#define T_DIM 1024
#define F_DIM 1024
#define D_DIM 16
#define CHUNK 128
#define NCHUNK (F_DIM / CHUNK)   // 8
#define T_PER_BLOCK 8

// ---------------------------------------------------------------------------
// Single fused kernel, sync-free prologue.
//
// Each warp w (== chunk c) computes its own shift redundantly:
//   - 32 lanes compute 4 rounded products dm*df each into smem (f-ordered),
//   - __syncwarp, lane 0 runs the sequential __fadd_rn chain over f=0..127
//     (the exact order verified rel_err == 0.0), trunc/clamp,
//   - shuffle-broadcast to the warp.
// No __syncthreads, no atomics, no global state -> graph-replay safe.
//
// The 64 (p==0, tb==0) blocks also write the delays output tail.
// Gather body identical to the proven 83.2us version (float4 __ldg + plain
// float4 stores).
// grid = B*D*P*(T/T_PER_BLOCK) = 16384 blocks, 256 threads.
// ---------------------------------------------------------------------------
__global__ __launch_bounds__(256)
void dedisp_fused_kernel(const float4* __restrict__ x,
                         float4*       __restrict__ out,
                         const float*  __restrict__ dm,
                         const float*  __restrict__ df,
                         float*        __restrict__ delays)
{
    const int bi = blockIdx.x;
    const int tb = bi & (T_DIM / T_PER_BLOCK - 1);   // 0..127
    const int p  = (bi >> 7) & (P_DIM - 1);
    const int d  = (bi >> 8) & (D_DIM - 1);
    const int b  = bi >> 12;
    const int bd = b * D_DIM + d;

    const int tid  = threadIdx.x;         // 0..255, f4 index
    const int c    = tid >> 5;            // chunk = warp id
    const int lane = tid & 31;

    __shared__ float sh[NCHUNK][CHUNK];   // per-warp product staging (4 KB)

    // --- warp-local shift computation (no cross-warp sync) ----------------
    const float dmv = dm[bd];
    {
        const float* base = df + c * CHUNK;
        #pragma unroll
        for (int j = 0; j < 4; j++) {
            const int i = lane + j * 32;
            sh[c][i] = __fmul_rn(dmv, base[i]);   // rounded product, f-ordered
        }
    }
    __syncwarp();

    int s;
    if (lane == 0) {
        float sum = 0.0f;
        #pragma unroll 16
        for (int i = 0; i < CHUNK; i++)
            sum = __fadd_rn(sum, sh[c][i]);       // sequential rounded adds
        const float mean = __fmul_rn(sum, 0.0078125f);   // exact *2^-7
        s = (int)truncf(mean);
        if (s < 0) s = 0;
        s &= (T_DIM - 1);
    }
    s = __shfl_sync(0xffffffffu, s, 0);

    // --- delays tail: 64 blocks, coalesced, independent of shifts ---------
    if (p == 0 && tb == 0) {
        float* drow = delays + (size_t)bd * F_DIM;
        #pragma unroll
        for (int j = 0; j < 4; j++) {
            const int f = tid + j * 256;
            drow[f] = __fmul_rn(dmv, df[f]);
        }
    }

    // --- gather-copy: 8 float4 rows per thread (identical to 83.2us body) --
    const int F4 = F_DIM / 4;             // 256 float4 per row

    const float4* __restrict__ xrow =
        x + (size_t)(b * P_DIM + p) * T_DIM * F4;

    float4* __restrict__ orow =
        out + ((size_t)(bd * P_DIM + p) * T_DIM
               + (size_t)tb * T_PER_BLOCK) * F4 + tid;

    const int t0 = tb * T_PER_BLOCK;

    #pragma unroll
    for (int k = 0; k < T_PER_BLOCK; k++) {
        int ts = t0 + k + s;
        if (ts >= T_DIM) ts -= T_DIM;     // s < 1024, t < 1024 -> one subtract
        orow[k * F4] = __ldg(&xrow[(size_t)ts * F4 + tid]);
    }
}

// ---------------------------------------------------------------------------
// Launch: ONE kernel, one graph node.
// ---------------------------------------------------------------------------
extern "C" void kernel_launch(void* const* d_in, const int* in_sizes, int n_in,
                              void* d_out, int out_size)
{
    const float* x  = (const float*)d_in[0];   // (4,2,1024,1024)
    const float* dm = (const float*)d_in[1];   // (4,16)
    const float* df = (const float*)d_in[2];   // (1024,)

    float* out = (float*)d_out;
    // Output layout: dedispersed (4,16,2,1024,1024) then delays (4,16,1024)
    float* delays = out + (size_t)B_DIM * D_DIM * P_DIM * T_DIM * F_DIM;

    const int nblocks = B_DIM * D_DIM * P_DIM * (T_DIM / T_PER_BLOCK); // 16384
    dedisp_fused_kernel<<<nblocks, 256>>>((const float4*)x, (float4*)out,
                                          dm, df, delays);
}

// round 17
// speedup vs baseline: 1.0424x; 1.0424x over previous
#include <cuda_runtime.h>
#include <cstdint>

// Problem constants (fixed shapes per reference)
#define B_DIM 4
#define P_DIM 2
#define T_DIM 1024
#define F_DIM 1024
#define D_DIM 16
#define CHUNK 128
#define NCHUNK (F_DIM / CHUNK)   // 8
#define T_PER_BLOCK 8

// Per-(b,d,chunk) integer shifts. 4*16*8 = 512 ints.
__device__ int g_shift[B_DIM * D_DIM * NCHUNK];

// ---------------------------------------------------------------------------
// Kernel 1: one WARP per (bd, chunk). 64 blocks x 256 threads (8 warps).
// Lane k of warp c loads df[c*128 + 4k .. 4k+3] as one float4, computes the
// rounded products (__fmul_rn, reference order), writes the delays slice
// coalesced, then the warp runs the sequential __fadd_rn chain over
// f = 0..127 via shuffles -- identical summation order to the verified
// rel_err == 0.0 implementation, but with a ~520-cycle critical path
// instead of ~4200 (no LDS in the chain).
// ---------------------------------------------------------------------------
__global__ __launch_bounds__(256)
void dedisp_prep_kernel(const float* __restrict__ dm,
                        const float4* __restrict__ df4,
                        float4* __restrict__ delays4)
{
    const int bd   = blockIdx.x;              // 0..63 : (b*16 + d)
    const int c    = threadIdx.x >> 5;        // chunk 0..7 (warp id)
    const int lane = threadIdx.x & 31;

    const float dmv = dm[bd];

    // lane k holds f = c*128 + 4k .. 4k+3
    const float4 dv = df4[c * 32 + lane];
    float4 pr;
    pr.x = __fmul_rn(dmv, dv.x);
    pr.y = __fmul_rn(dmv, dv.y);
    pr.z = __fmul_rn(dmv, dv.z);
    pr.w = __fmul_rn(dmv, dv.w);

    // delays output slice: coalesced float4 stores
    delays4[(size_t)bd * (F_DIM / 4) + c * 32 + lane] = pr;

    // Sequential rounded-add chain over f = 0..127 (exact reference order).
    float sum = 0.0f;
    #pragma unroll
    for (int j = 0; j < 32; j++) {
        const float a0 = __shfl_sync(0xffffffffu, pr.x, j);
        const float a1 = __shfl_sync(0xffffffffu, pr.y, j);
        const float a2 = __shfl_sync(0xffffffffu, pr.z, j);
        const float a3 = __shfl_sync(0xffffffffu, pr.w, j);
        sum = __fadd_rn(sum, a0);
        sum = __fadd_rn(sum, a1);
        sum = __fadd_rn(sum, a2);
        sum = __fadd_rn(sum, a3);
    }

    if (lane == 0) {
        const float mean = __fmul_rn(sum, 0.0078125f);   // exact *2^-7
        int s = (int)truncf(mean);
        if (s < 0) s = 0;
        g_shift[bd * NCHUNK + c] = s & (T_DIM - 1);
    }
}

// ---------------------------------------------------------------------------
// Kernel 2: the gather-copy -- byte-identical to the proven 83.2us kernel.
// grid = B*D*P*(T/T_PER_BLOCK) = 16384 blocks, 256 threads.
// Warp w handles chunk w -> shift is warp-uniform.
// ---------------------------------------------------------------------------
__global__ __launch_bounds__(256)
void dedisp_gather_kernel(const float4* __restrict__ x,
                          float4* __restrict__ out)
{
    const int bi  = blockIdx.x;
    const int tb  = bi & (T_DIM / T_PER_BLOCK - 1);   // 0..127
    const int p   = (bi >> 7) & (P_DIM - 1);
    const int d   = (bi >> 8) & (D_DIM - 1);
    const int b   = bi >> 12;

    const int tid = threadIdx.x;          // 0..255, f4 index
    const int c   = tid >> 5;             // chunk = warp id

    const int s = g_shift[(b * D_DIM + d) * NCHUNK + c];

    const int F4 = F_DIM / 4;             // 256 float4 per row

    const float4* __restrict__ xrow =
        x + (size_t)(b * P_DIM + p) * T_DIM * F4;

    float4* __restrict__ orow =
        out + ((size_t)((b * D_DIM + d) * P_DIM + p) * T_DIM
               + (size_t)tb * T_PER_BLOCK) * F4 + tid;

    const int t0 = tb * T_PER_BLOCK;

    #pragma unroll
    for (int k = 0; k < T_PER_BLOCK; k++) {
        int ts = t0 + k + s;
        if (ts >= T_DIM) ts -= T_DIM;     // s < 1024, t < 1024 -> one subtract
        orow[k * F4] = __ldg(&xrow[(size_t)ts * F4 + tid]);
    }
}

// ---------------------------------------------------------------------------
// Launch: two plain sequential graph nodes.
// ---------------------------------------------------------------------------
extern "C" void kernel_launch(void* const* d_in, const int* in_sizes, int n_in,
                              void* d_out, int out_size)
{
    const float* x  = (const float*)d_in[0];   // (4,2,1024,1024)
    const float* dm = (const float*)d_in[1];   // (4,16)
    const float* df = (const float*)d_in[2];   // (1024,)

    float* out = (float*)d_out;
    // Output layout: dedispersed (4,16,2,1024,1024) then delays (4,16,1024)
    float* delays = out + (size_t)B_DIM * D_DIM * P_DIM * T_DIM * F_DIM;

    dedisp_prep_kernel<<<B_DIM * D_DIM, 256>>>(dm, (const float4*)df,
                                               (float4*)delays);

    const int nblocks = B_DIM * D_DIM * P_DIM * (T_DIM / T_PER_BLOCK); // 16384
    dedisp_gather_kernel<<<nblocks, 256>>>((const float4*)x, (float4*)out);
}